// round 11
// baseline (speedup 1.0000x reference)
#include <cuda_runtime.h>

#define SEQ 2048
#define BATCH 1024
#define UF2 2
#define MASK 0xFFFFFFFFu

typedef unsigned long long ull;

__device__ __forceinline__ float tanh_ap(float x) {
    float y;
    asm("tanh.approx.f32 %0, %1;" : "=f"(y) : "f"(x));
    return y;
}
__device__ __forceinline__ ull pk(float lo, float hi) {
    ull r;
    asm("mov.b64 %0, {%1, %2};" : "=l"(r) : "f"(lo), "f"(hi));
    return r;
}
__device__ __forceinline__ void upk(float& lo, float& hi, ull v) {
    asm("mov.b64 {%0, %1}, %2;" : "=f"(lo), "=f"(hi) : "l"(v));
}
__device__ __forceinline__ ull fma2(ull a, ull b, ull c) {
    ull d;
    asm("fma.rn.f32x2 %0, %1, %2, %3;" : "=l"(d) : "l"(a), "l"(b), "l"(c));
    return d;
}
__device__ __forceinline__ void store_pred(int flag, float* p, float v) {
    asm volatile(
        "{\n\t.reg .pred %%pp;\n\t"
        "setp.ne.s32 %%pp, %0, 0;\n\t"
        "@%%pp st.global.f32 [%1], %2;\n\t}"
        :: "r"(flag), "l"(p), "f"(v));
}

struct LaneState {
    ull wi_if[4], wi_go[4], wh_if[4], wh_go[4];  // packed (i,f)/(g,o), pre-scaled
    ull b_if, b_go;
    float hA, hB, c;      // layer lanes: h(t0),h(t1) as 2h, c plain. feeder: x pair.
    float rw0, rw1, rw2, rw3, rb;
    int l, bh, bi, b;
    int isfeed, flagA, flagB;
};

// One LSTM cell sub-step. f32x2 dots (two parallel 4-deep chains), plain-c
// epilogue, MUFU issued in c-chain priority order (tf first, to last).
__device__ __forceinline__ void substep(
    const LaneState& s,
    float iv0, float iv1, float iv2, float iv3,
    float hv0, float hv1, float hv2, float hv3,
    float c_in, float& nc, float& nh)
{
    const ull di0 = pk(iv0, iv0), di1 = pk(iv1, iv1);
    const ull di2 = pk(iv2, iv2), di3 = pk(iv3, iv3);
    const ull dh0 = pk(hv0, hv0), dh1 = pk(hv1, hv1);
    const ull dh2 = pk(hv2, hv2), dh3 = pk(hv3, hv3);

    // h-chains (critical) and iv-chains (early data) in parallel.
    ull pif = fma2(s.wh_if[0], dh0, pk(0.f, 0.f));
    ull pgo = fma2(s.wh_go[0], dh0, pk(0.f, 0.f));
    ull aif = fma2(s.wi_if[0], di0, s.b_if);
    ull ago = fma2(s.wi_go[0], di0, s.b_go);
    pif = fma2(s.wh_if[1], dh1, pif); pgo = fma2(s.wh_go[1], dh1, pgo);
    aif = fma2(s.wi_if[1], di1, aif); ago = fma2(s.wi_go[1], di1, ago);
    pif = fma2(s.wh_if[2], dh2, pif); pgo = fma2(s.wh_go[2], dh2, pgo);
    aif = fma2(s.wi_if[2], di2, aif); ago = fma2(s.wi_go[2], di2, ago);
    pif = fma2(s.wh_if[3], dh3, pif); pgo = fma2(s.wh_go[3], dh3, pgo);
    aif = fma2(s.wi_if[3], di3, aif); ago = fma2(s.wi_go[3], di3, ago);

    const ull sif = fma2(pk(1.f, 1.f), pif, aif);   // (pre_i, pre_f)*0.5-folded
    const ull sgo = fma2(pk(1.f, 1.f), pgo, ago);   // (pre_g, pre_o)

    float gi, gf, gg, go;
    upk(gi, gf, sif);
    upk(gg, go, sgo);

    // MUFU priority: forget gate first (c-recurrence), output gate last.
    const float tf = tanh_ap(gf);
    const float ti = tanh_ap(gi);
    const float cc = tanh_ap(gg);
    const float to = tanh_ap(go);

    // nc = sigm(f)*c + sigm(i)*cc = 0.5*(tf*c+c) + 0.5*(ti*cc+cc)
    const float u = fmaf(tf, c_in, c_in);
    const float w = 0.5f * fmaf(ti, cc, cc);
    nc = fmaf(0.5f, u, w);
    const float th = tanh_ap(nc);
    nh = fmaf(to, th, th);               // 2*h_new
}

// Tick k: layer l does timesteps t0=2(k-l), t1=t0+1. Group 6 = feeder
// holding (x_even, x_odd) in (hA,hB); group 7 = head (bi=20).
template<bool Guarded>
__device__ __forceinline__ void tick(int k, LaneState& s,
                                     float& xslotA, float& xslotB,
                                     const float* __restrict__ xq,
                                     float* __restrict__ out)
{
    // Front shfls: own-group h(t-1) first (critical), then step inputs.
    const float hv0 = __shfl_sync(MASK, s.hB, s.bh + 0);
    const float hv1 = __shfl_sync(MASK, s.hB, s.bh + 1);
    const float hv2 = __shfl_sync(MASK, s.hB, s.bh + 2);
    const float hv3 = __shfl_sync(MASK, s.hB, s.bh + 3);
    const float ivA0 = __shfl_sync(MASK, s.hA, s.bi + 0);
    const float ivA1 = __shfl_sync(MASK, s.hA, s.bi + 1);
    const float ivA2 = __shfl_sync(MASK, s.hA, s.bi + 2);
    const float ivA3 = __shfl_sync(MASK, s.hA, s.bi + 3);
    const float ivB0 = __shfl_sync(MASK, s.hB, s.bi + 0);
    const float ivB1 = __shfl_sync(MASK, s.hB, s.bi + 1);
    const float ivB2 = __shfl_sync(MASK, s.hB, s.bi + 2);
    const float ivB3 = __shfl_sync(MASK, s.hB, s.bi + 3);

    float ncA, nhA;
    substep(s, ivA0, ivA1, ivA2, ivA3, hv0, hv1, hv2, hv3, s.c, ncA, nhA);

    // Mid-tick exchange of step-A h within own group.
    const float mh0 = __shfl_sync(MASK, nhA, s.bh + 0);
    const float mh1 = __shfl_sync(MASK, nhA, s.bh + 1);
    const float mh2 = __shfl_sync(MASK, nhA, s.bh + 2);
    const float mh3 = __shfl_sync(MASK, nhA, s.bh + 3);

    float ncB, nhB;
    substep(s, ivB0, ivB1, ivB2, ivB3, mh0, mh1, mh2, mh3, ncA, ncB, nhB);

    // Head (group 7 sees layer-5 h pair in ivA/ivB). Lane 28: t0, lane 29: t1.
    {
        float yA = s.rb, yB = s.rb;
        yA = fmaf(s.rw0, ivA0, yA); yB = fmaf(s.rw0, ivB0, yB);
        yA = fmaf(s.rw1, ivA1, yA); yB = fmaf(s.rw1, ivB1, yB);
        yA = fmaf(s.rw2, ivA2, yA); yB = fmaf(s.rw2, ivB2, yB);
        yA = fmaf(s.rw3, ivA3, yA); yB = fmaf(s.rw3, ivB3, yB);
        const int kh = k - 6;
        const int hok = Guarded ? ((unsigned)kh <= 1023) : 1;
        const int t0 = Guarded ? ((kh < 0 ? 0 : (kh > 1023 ? 1023 : kh)) * 2) : kh * 2;
        store_pred(s.flagA & hok, out + (size_t)t0 * BATCH + s.b, yA);
        store_pred(s.flagB & hok, out + (size_t)(t0 + 1) * BATCH + s.b, yB);
    }

    // Feeder refill: consume x pair, prefetch pair for tick k+1+UF2.
    const float xA = xslotA, xB = xslotB;
    {
        int tp = 2 * (k + 1 + UF2);
        int tpA = tp, tpB = tp + 1;
        if (Guarded) { tpA = tpA > 2046 ? 2046 : tpA; tpB = tpB > 2047 ? 2047 : tpB; }
        xslotA = __ldg(xq + (size_t)tpA * BATCH * 4);
        xslotB = __ldg(xq + (size_t)tpB * BATCH * 4);
    }

    const int valid = Guarded ? ((unsigned)(k - s.l) <= 1023) : 1;
    const float selA = valid ? nhA : s.hA;
    const float selB = valid ? nhB : s.hB;
    const float selC = valid ? ncB : s.c;
    s.hA = s.isfeed ? xA : selA;
    s.hB = s.isfeed ? xB : selB;
    s.c  = s.isfeed ? s.c : selC;
}

__global__ __launch_bounds__(32) void lstm_reg_kernel(
    const float* __restrict__ x,      // [S, B, 4]
    const float* __restrict__ w_ih,   // [6, 16, 4]
    const float* __restrict__ w_hh,   // [6, 16, 4]
    const float* __restrict__ b_ih,   // [6, 16]
    const float* __restrict__ b_hh,   // [6, 16]
    const float* __restrict__ reg_w,  // [1, 4]
    const float* __restrict__ reg_b,  // [1]
    float* __restrict__ out)          // [S, B, 1]
{
    const int lane = threadIdx.x & 31;

    LaneState s;
    s.b = blockIdx.x;
    s.l = lane >> 2;                  // 0..5 layers, 6 feeder, 7 head
    const int j = lane & 3;
    s.bh = s.l * 4;
    s.bi = (s.l == 0) ? 24 : ((s.l == 7) ? 20 : (s.l - 1) * 4);
    s.isfeed = (s.l == 6);
    s.flagA = (lane == 28);
    s.flagB = (lane == 29);

    float wi[4][4], wh[4][4], bb[4];
#pragma unroll
    for (int g = 0; g < 4; ++g) {
#pragma unroll
        for (int i = 0; i < 4; ++i) { wi[g][i] = 0.f; wh[g][i] = 0.f; }
        bb[g] = 0.f;
    }
    if (s.l < 6) {
#pragma unroll
        for (int g = 0; g < 4; ++g) {
            const int row = s.l * 16 + g * 4 + j;       // gate order i,f,g,o
            const float gsc = (g == 2) ? 1.0f : 0.5f;   // sigmoid-as-tanh fold
            const float isc = (s.l == 0) ? 1.0f : 0.5f; // input is 2h for layers>0
#pragma unroll
            for (int i = 0; i < 4; ++i) {
                wi[g][i] = w_ih[row * 4 + i] * gsc * isc;
                wh[g][i] = w_hh[row * 4 + i] * gsc * 0.5f;  // own h is 2h
            }
            bb[g] = (b_ih[row] + b_hh[row]) * gsc;
        }
    }
#pragma unroll
    for (int m = 0; m < 4; ++m) {
        s.wi_if[m] = pk(wi[0][m], wi[1][m]);
        s.wi_go[m] = pk(wi[2][m], wi[3][m]);
        s.wh_if[m] = pk(wh[0][m], wh[1][m]);
        s.wh_go[m] = pk(wh[2][m], wh[3][m]);
    }
    s.b_if = pk(bb[0], bb[1]);
    s.b_go = pk(bb[2], bb[3]);

    s.rw0 = reg_w[0] * 0.5f; s.rw1 = reg_w[1] * 0.5f;
    s.rw2 = reg_w[2] * 0.5f; s.rw3 = reg_w[3] * 0.5f;
    s.rb  = reg_b[0];

    s.hA = 0.f; s.hB = 0.f; s.c = 0.f;
    const float* xq = x + (size_t)s.b * 4 + j;
    if (s.isfeed) {
        s.hA = xq[0];
        s.hB = xq[(size_t)BATCH * 4];
    }

    // Prefetch ring (UF2 deep): slot u holds x pair for tick ≡ u (mod UF2).
    float xbufA[UF2], xbufB[UF2];
#pragma unroll
    for (int u = 0; u < UF2; ++u) {
        xbufA[u] = xq[(size_t)(2 * (u + 1)) * BATCH * 4];
        xbufB[u] = xq[(size_t)(2 * (u + 1) + 1) * BATCH * 4];
    }

    // ---- fill: ticks 0..7 (guarded) ----
#pragma unroll
    for (int u = 0; u < 8; ++u)
        tick<true>(u, s, xbufA[u & (UF2 - 1)], xbufB[u & (UF2 - 1)], xq, out);

    // ---- main: ticks 8..1015, guard-free ----
#pragma unroll 1
    for (int kc = 8; kc < 1016; kc += UF2) {
#pragma unroll
        for (int u = 0; u < UF2; ++u)
            tick<false>(kc + u, s, xbufA[u], xbufB[u], xq, out);
    }

    // ---- drain: ticks 1016..1029 (guarded) ----
#pragma unroll 1
    for (int kc = 1016; kc < 1016 + 16; kc += UF2) {
#pragma unroll
        for (int u = 0; u < UF2; ++u) {
            const int k = kc + u;
            if (k < 1030)
                tick<true>(k, s, xbufA[u], xbufB[u], xq, out);
        }
    }
}

extern "C" void kernel_launch(void* const* d_in, const int* in_sizes, int n_in,
                              void* d_out, int out_size) {
    const float* x     = (const float*)d_in[0];
    const float* w_ih  = (const float*)d_in[1];
    const float* w_hh  = (const float*)d_in[2];
    const float* b_ih  = (const float*)d_in[3];
    const float* b_hh  = (const float*)d_in[4];
    const float* reg_w = (const float*)d_in[5];
    const float* reg_b = (const float*)d_in[6];
    float* out = (float*)d_out;

    lstm_reg_kernel<<<1024, 32>>>(x, w_ih, w_hh, b_ih, b_hh, reg_w, reg_b, out);
}

// round 12
// speedup vs baseline: 1.2779x; 1.2779x over previous
#include <cuda_runtime.h>

#define SEQ 2048
#define BATCH 1024
#define UF2 4
#define MASK 0xFFFFFFFFu

typedef unsigned long long ull;

__device__ __forceinline__ float tanh_ap(float x) {
    float y;
    asm("tanh.approx.f32 %0, %1;" : "=f"(y) : "f"(x));
    return y;
}
__device__ __forceinline__ ull pk(float lo, float hi) {
    ull r;
    asm("mov.b64 %0, {%1, %2};" : "=l"(r) : "f"(lo), "f"(hi));
    return r;
}
__device__ __forceinline__ void upk(float& lo, float& hi, ull v) {
    asm("mov.b64 {%0, %1}, %2;" : "=f"(lo), "=f"(hi) : "l"(v));
}
__device__ __forceinline__ ull fma2(ull a, ull b, ull c) {
    ull d;
    asm("fma.rn.f32x2 %0, %1, %2, %3;" : "=l"(d) : "l"(a), "l"(b), "l"(c));
    return d;
}
__device__ __forceinline__ void store_pred(int flag, float* p, float v) {
    asm volatile(
        "{\n\t.reg .pred %%pp;\n\t"
        "setp.ne.s32 %%pp, %0, 0;\n\t"
        "@%%pp st.global.f32 [%1], %2;\n\t}"
        :: "r"(flag), "l"(p), "f"(v));
}

struct LaneState {
    ull wi_if[4], wi_go[4], wh_if[4], wh_go[4];  // packed (i,f)/(g,o), pre-scaled
    ull b_if, b_go;
    float hB, c2;         // h(t1) as 2h (feeder: x odd); c2 = 2c
    float ivA0, ivA1, ivA2, ivA3;   // pipelined step-A input (prev layer hA / x even)
    float rw0, rw1, rw2, rw3, rb;
    int l, bh, bi, b;
    int isfeed, flagA, flagB;
};

// One LSTM cell sub-step — byte-identical math to the R6 kernel (230us, passed).
__device__ __forceinline__ void substep(
    const LaneState& s,
    float iv0, float iv1, float iv2, float iv3,
    float hv0, float hv1, float hv2, float hv3,
    float c2_in, float& nc2, float& nh)
{
    const ull dv_i0 = pk(iv0, iv0), dv_i1 = pk(iv1, iv1);
    const ull dv_i2 = pk(iv2, iv2), dv_i3 = pk(iv3, iv3);
    const ull dv_h0 = pk(hv0, hv0), dv_h1 = pk(hv1, hv1);
    const ull dv_h2 = pk(hv2, hv2), dv_h3 = pk(hv3, hv3);

    ull acc_if = s.b_if, acc_go = s.b_go;
    acc_if = fma2(s.wi_if[0], dv_i0, acc_if); acc_go = fma2(s.wi_go[0], dv_i0, acc_go);
    acc_if = fma2(s.wi_if[1], dv_i1, acc_if); acc_go = fma2(s.wi_go[1], dv_i1, acc_go);
    acc_if = fma2(s.wi_if[2], dv_i2, acc_if); acc_go = fma2(s.wi_go[2], dv_i2, acc_go);
    acc_if = fma2(s.wi_if[3], dv_i3, acc_if); acc_go = fma2(s.wi_go[3], dv_i3, acc_go);
    acc_if = fma2(s.wh_if[0], dv_h0, acc_if); acc_go = fma2(s.wh_go[0], dv_h0, acc_go);
    acc_if = fma2(s.wh_if[1], dv_h1, acc_if); acc_go = fma2(s.wh_go[1], dv_h1, acc_go);
    acc_if = fma2(s.wh_if[2], dv_h2, acc_if); acc_go = fma2(s.wh_go[2], dv_h2, acc_go);
    acc_if = fma2(s.wh_if[3], dv_h3, acc_if); acc_go = fma2(s.wh_go[3], dv_h3, acc_go);

    float gi, gf, gg, go;
    upk(gi, gf, acc_if);
    upk(gg, go, acc_go);

    const float ti = tanh_ap(gi);   // tanh(0.5*pre_i)
    const float tf = tanh_ap(gf);
    const float cc = tanh_ap(gg);   // tanh(pre_g)
    const float to = tanh_ap(go);

    // c2 = 2c: u = tf*c2+c2, v = ti*cc+cc; c2_new = 0.5u + v
    const ull uv = fma2(pk(tf, ti), pk(c2_in, cc), pk(c2_in, cc));
    float u, v;
    upk(u, v, uv);
    nc2 = fmaf(0.5f, u, v);
    const float th = tanh_ap(0.5f * nc2);
    nh = fmaf(to, th, th);          // 2*h_new
}

// Tick k: layer l does timesteps t0=2(k-l), t1=t0+1. Group 6 = feeder,
// group 7 = head (bi=20). Step-A input ivA* is PIPELINED: it was shuffled at
// mid-tick k-1 from nhA (or the feeder's pending x slot), so this tick's
// entry chain only waits on hB-dependent shuffles.
template<bool Guarded>
__device__ __forceinline__ void tick(int k, LaneState& s,
                                     float& xslotA, float& xslotB,
                                     const float* __restrict__ xq,
                                     float* __restrict__ out)
{
    // Front shfls (8): own-group h(t-1) and step-B input.
    const float hv0 = __shfl_sync(MASK, s.hB, s.bh + 0);
    const float hv1 = __shfl_sync(MASK, s.hB, s.bh + 1);
    const float hv2 = __shfl_sync(MASK, s.hB, s.bh + 2);
    const float hv3 = __shfl_sync(MASK, s.hB, s.bh + 3);
    const float ivB0 = __shfl_sync(MASK, s.hB, s.bi + 0);
    const float ivB1 = __shfl_sync(MASK, s.hB, s.bi + 1);
    const float ivB2 = __shfl_sync(MASK, s.hB, s.bi + 2);
    const float ivB3 = __shfl_sync(MASK, s.hB, s.bi + 3);

    const float ivA0 = s.ivA0, ivA1 = s.ivA1, ivA2 = s.ivA2, ivA3 = s.ivA3;

    float ncA, nhA;
    substep(s, ivA0, ivA1, ivA2, ivA3, hv0, hv1, hv2, hv3, s.c2, ncA, nhA);

    // Mid-tick shuffles (8): step-B own-group h AND next tick's step-A input.
    const float mh0 = __shfl_sync(MASK, nhA, s.bh + 0);
    const float mh1 = __shfl_sync(MASK, nhA, s.bh + 1);
    const float mh2 = __shfl_sync(MASK, nhA, s.bh + 2);
    const float mh3 = __shfl_sync(MASK, nhA, s.bh + 3);
    const float srcA = s.isfeed ? xslotA : nhA;   // next hA on this lane
    s.ivA0 = __shfl_sync(MASK, srcA, s.bi + 0);
    s.ivA1 = __shfl_sync(MASK, srcA, s.bi + 1);
    s.ivA2 = __shfl_sync(MASK, srcA, s.bi + 2);
    s.ivA3 = __shfl_sync(MASK, srcA, s.bi + 3);

    float ncB, nhB;
    substep(s, ivB0, ivB1, ivB2, ivB3, mh0, mh1, mh2, mh3, ncA, ncB, nhB);

    // Head (group 7 sees layer-5 h pair in ivA/ivB). Lane 28: t0, lane 29: t1.
    {
        float yA = s.rb, yB = s.rb;
        yA = fmaf(s.rw0, ivA0, yA); yB = fmaf(s.rw0, ivB0, yB);
        yA = fmaf(s.rw1, ivA1, yA); yB = fmaf(s.rw1, ivB1, yB);
        yA = fmaf(s.rw2, ivA2, yA); yB = fmaf(s.rw2, ivB2, yB);
        yA = fmaf(s.rw3, ivA3, yA); yB = fmaf(s.rw3, ivB3, yB);
        const int kh = k - 6;
        const int hok = Guarded ? ((unsigned)kh <= 1023) : 1;
        const int t0 = Guarded ? ((kh < 0 ? 0 : (kh > 1023 ? 1023 : kh)) * 2) : kh * 2;
        store_pred(s.flagA & hok, out + (size_t)t0 * BATCH + s.b, yA);
        store_pred(s.flagB & hok, out + (size_t)(t0 + 1) * BATCH + s.b, yB);
    }

    // Feeder refill: consume x pair, prefetch pair for tick k+1+UF2.
    const float xB = xslotB;
    {
        int tp = 2 * (k + 1 + UF2);
        int tpA = tp, tpB = tp + 1;
        if (Guarded) { tpA = tpA > 2046 ? 2046 : tpA; tpB = tpB > 2047 ? 2047 : tpB; }
        xslotA = __ldg(xq + (size_t)tpA * BATCH * 4);
        xslotB = __ldg(xq + (size_t)tpB * BATCH * 4);
    }

    const int valid = Guarded ? ((unsigned)(k - s.l) <= 1023) : 1;
    const float selB = valid ? nhB : s.hB;
    const float selC = valid ? ncB : s.c2;
    s.hB = s.isfeed ? xB : selB;
    s.c2 = s.isfeed ? s.c2 : selC;
}

__global__ __launch_bounds__(32) void lstm_reg_kernel(
    const float* __restrict__ x,      // [S, B, 4]
    const float* __restrict__ w_ih,   // [6, 16, 4]
    const float* __restrict__ w_hh,   // [6, 16, 4]
    const float* __restrict__ b_ih,   // [6, 16]
    const float* __restrict__ b_hh,   // [6, 16]
    const float* __restrict__ reg_w,  // [1, 4]
    const float* __restrict__ reg_b,  // [1]
    float* __restrict__ out)          // [S, B, 1]
{
    const int lane = threadIdx.x & 31;

    LaneState s;
    s.b = blockIdx.x;
    s.l = lane >> 2;                  // 0..5 layers, 6 feeder, 7 head
    const int j = lane & 3;
    s.bh = s.l * 4;
    s.bi = (s.l == 0) ? 24 : ((s.l == 7) ? 20 : (s.l - 1) * 4);
    s.isfeed = (s.l == 6);
    s.flagA = (lane == 28);
    s.flagB = (lane == 29);

    float wi[4][4], wh[4][4], bb[4];
#pragma unroll
    for (int g = 0; g < 4; ++g) {
#pragma unroll
        for (int i = 0; i < 4; ++i) { wi[g][i] = 0.f; wh[g][i] = 0.f; }
        bb[g] = 0.f;
    }
    if (s.l < 6) {
#pragma unroll
        for (int g = 0; g < 4; ++g) {
            const int row = s.l * 16 + g * 4 + j;       // gate order i,f,g,o
            const float gsc = (g == 2) ? 1.0f : 0.5f;   // sigmoid-as-tanh fold
            const float isc = (s.l == 0) ? 1.0f : 0.5f; // input is 2h for layers>0
#pragma unroll
            for (int i = 0; i < 4; ++i) {
                wi[g][i] = w_ih[row * 4 + i] * gsc * isc;
                wh[g][i] = w_hh[row * 4 + i] * gsc * 0.5f;  // own h is 2h
            }
            bb[g] = (b_ih[row] + b_hh[row]) * gsc;
        }
    }
#pragma unroll
    for (int m = 0; m < 4; ++m) {
        s.wi_if[m] = pk(wi[0][m], wi[1][m]);
        s.wi_go[m] = pk(wi[2][m], wi[3][m]);
        s.wh_if[m] = pk(wh[0][m], wh[1][m]);
        s.wh_go[m] = pk(wh[2][m], wh[3][m]);
    }
    s.b_if = pk(bb[0], bb[1]);
    s.b_go = pk(bb[2], bb[3]);

    s.rw0 = reg_w[0] * 0.5f; s.rw1 = reg_w[1] * 0.5f;
    s.rw2 = reg_w[2] * 0.5f; s.rw3 = reg_w[3] * 0.5f;
    s.rb  = reg_b[0];

    s.hB = 0.f; s.c2 = 0.f;
    const float* xq = x + (size_t)s.b * 4 + j;
    if (s.isfeed) s.hB = xq[(size_t)BATCH * 4];   // x[1] components

    // Pre-shuffle initial step-A input (tick 0): feeder holds x[0], layers 0.
    {
        const float src0 = s.isfeed ? xq[0] : 0.f;
        s.ivA0 = __shfl_sync(MASK, src0, s.bi + 0);
        s.ivA1 = __shfl_sync(MASK, src0, s.bi + 1);
        s.ivA2 = __shfl_sync(MASK, src0, s.bi + 2);
        s.ivA3 = __shfl_sync(MASK, src0, s.bi + 3);
    }

    // Prefetch ring: slot u holds x pair consumed at tick k ≡ u (mod UF2),
    // i.e. x[2(k+1)], x[2(k+1)+1].
    float xbufA[UF2], xbufB[UF2];
#pragma unroll
    for (int u = 0; u < UF2; ++u) {
        xbufA[u] = xq[(size_t)(2 * (u + 1)) * BATCH * 4];
        xbufB[u] = xq[(size_t)(2 * (u + 1) + 1) * BATCH * 4];
    }

    // ---- fill: ticks 0..7 (guarded) ----
#pragma unroll
    for (int u = 0; u < 8; ++u)
        tick<true>(u, s, xbufA[u & (UF2 - 1)], xbufB[u & (UF2 - 1)], xq, out);

    // ---- main: ticks 8..1015, guard-free ----
#pragma unroll 1
    for (int kc = 8; kc < 1016; kc += UF2) {
#pragma unroll
        for (int u = 0; u < UF2; ++u)
            tick<false>(kc + u, s, xbufA[u], xbufB[u], xq, out);
    }

    // ---- drain: ticks 1016..1029 (guarded) ----
#pragma unroll 1
    for (int kc = 1016; kc < 1016 + 16; kc += UF2) {
#pragma unroll
        for (int u = 0; u < UF2; ++u) {
            const int k = kc + u;
            if (k < 1030)
                tick<true>(k, s, xbufA[u], xbufB[u], xq, out);
        }
    }
}

extern "C" void kernel_launch(void* const* d_in, const int* in_sizes, int n_in,
                              void* d_out, int out_size) {
    const float* x     = (const float*)d_in[0];
    const float* w_ih  = (const float*)d_in[1];
    const float* w_hh  = (const float*)d_in[2];
    const float* b_ih  = (const float*)d_in[3];
    const float* b_hh  = (const float*)d_in[4];
    const float* reg_w = (const float*)d_in[5];
    const float* reg_b = (const float*)d_in[6];
    float* out = (float*)d_out;

    lstm_reg_kernel<<<1024, 32>>>(x, w_ih, w_hh, b_ih, b_hh, reg_w, reg_b, out);
}